// round 6
// baseline (speedup 1.0000x reference)
#include <cuda_runtime.h>
#include <math.h>

// Problem constants (fixed by the dataset: a=b=8192, e1=e2=c=m=1024)
#define NROWS 8192
#define MDIM  1024
#define KD    1024

// ---------------- scratch (device globals; no allocation allowed) ----------
__device__ float g_p[2][NROWS * MDIM];       // p1 / p2   (64 MB total)
__device__ float g_bias[2][MDIM];            // b + Wc @ ctx
__device__ float g_cparts[2][64][MDIM];      // colsum partials (per 128-row chunk)
__device__ float g_s[2][MDIM];               // s1 / s2
__device__ float g_logits[2][NROWS];         // attn logits
__device__ float g_stats[2][2];              // {max, sumexp} per side
__device__ float g_patt[2][64][MDIM];        // weighted-colsum partials

// ---------------- cp.async helpers -----------------------------------------
__device__ __forceinline__ void cp_async16(void* smem_dst, const void* gsrc) {
    unsigned saddr = (unsigned)__cvta_generic_to_shared(smem_dst);
    asm volatile("cp.async.cg.shared.global [%0], [%1], 16;\n" :: "r"(saddr), "l"(gsrc));
}
__device__ __forceinline__ void cp_commit()  { asm volatile("cp.async.commit_group;\n"); }
__device__ __forceinline__ void cp_wait0()   { asm volatile("cp.async.wait_group 0;\n"); }

// ---------------- ldmatrix wrapper (b16 x4 — used as 8x4-tf32 tiles) -------
__device__ __forceinline__ void ldsm_x4(unsigned& r0, unsigned& r1,
                                        unsigned& r2, unsigned& r3, const void* p) {
    unsigned addr = (unsigned)__cvta_generic_to_shared(p);
    asm volatile("ldmatrix.sync.aligned.m8n8.x4.shared.b16 {%0,%1,%2,%3}, [%4];\n"
                 : "=r"(r0), "=r"(r1), "=r"(r2), "=r"(r3) : "r"(addr));
}

// ---------------- kernel 1: bias[j] = b[j] + sum_c Wc[j,c]*ctx[c] ----------
__global__ void k_bias(const float* __restrict__ b1, const float* __restrict__ b2,
                       const float* __restrict__ Wc1, const float* __restrict__ Wc2,
                       const float* __restrict__ ctx) {
    int z = blockIdx.z, j = blockIdx.x, tx = threadIdx.x;
    const float* W = z ? Wc2 : Wc1;
    const float* b = z ? b2 : b1;
    float acc = 0.f;
    for (int c = tx; c < KD; c += 128) acc += W[j * KD + c] * ctx[c];
    __shared__ float sm[128];
    sm[tx] = acc; __syncthreads();
    for (int s = 64; s > 0; s >>= 1) { if (tx < s) sm[tx] += sm[tx + s]; __syncthreads(); }
    if (tx == 0) g_bias[z][j] = b[j] + sm[0];
}

// ---------------- tf32 mma.sync wrapper ------------------------------------
__device__ __forceinline__ void mma_tf32(float c[4], const unsigned a[4], const unsigned b[2]) {
    asm volatile(
        "mma.sync.aligned.m16n8k8.row.col.f32.tf32.tf32.f32 "
        "{%0,%1,%2,%3}, {%4,%5,%6,%7}, {%8,%9}, {%0,%1,%2,%3};\n"
        : "+f"(c[0]), "+f"(c[1]), "+f"(c[2]), "+f"(c[3])
        : "r"(a[0]), "r"(a[1]), "r"(a[2]), "r"(a[3]), "r"(b[0]), "r"(b[1]));
}

// ---------------- kernel 2: P = elu(X @ W^T + bias), fused colsum ----------
// CTA tile 128x128, KTILE=16, 256 threads = 8 warps; warp tile 64x32.
// Fragments gathered with ldmatrix.b16 (tf32 trick): 12 LDSM/ktile vs 48 LDS.
// Smem rows stride 20 floats = 80B: 16B-aligned rows, conflict-free phases.
__global__ void __launch_bounds__(256, 2)
k_gemm_elu(const float* __restrict__ X1, const float* __restrict__ X2,
           const float* __restrict__ Wm1, const float* __restrict__ Wm2) {
    const int z = blockIdx.z;
    const float* X = z ? X2 : X1;
    const float* W = z ? Wm2 : Wm1;
    float* P = g_p[z];
    const float* bias = g_bias[z];

    __shared__ float As[2][128][20];   // X tile, m-major, k padded 16->20
    __shared__ float Bs[2][128][20];   // W tile, n-major, k padded

    const int tid  = threadIdx.x;
    const int brow = blockIdx.y, bcol = blockIdx.x;
    const int lr = tid >> 2, lc = tid & 3;         // cp.async fill mapping
    const int warp = tid >> 5, lane = tid & 31;
    const int g = lane >> 2, tg = lane & 3;        // mma lane decomposition
    const int wm = warp & 1, wn = warp >> 1;

    // ldmatrix per-lane tile decomposition: t = lane>>3 (tile), r = lane&7 (row)
    const int t = lane >> 3, r = lane & 7;
    const int aRow = wm * 64 + (t & 1) * 8 + r;    // A: tiles {m+0,m+8} x {k0,k0+4}
    const int aK   = (t >> 1) * 4;
    const int bRow = wn * 32 + (t >> 1) * 8 + r;   // B: tiles {k0,k0+4} x {n+0,n+8}
    const int bK   = (t & 1) * 4;

    const float* Xg = X + (size_t)(brow * 128 + lr) * KD + lc * 4;
    const float* Wg = W + (size_t)(bcol * 128 + lr) * KD + lc * 4;

    float acc[4][4][4];
    #pragma unroll
    for (int mi = 0; mi < 4; mi++)
        #pragma unroll
        for (int ni = 0; ni < 4; ni++)
            #pragma unroll
            for (int q = 0; q < 4; q++) acc[mi][ni][q] = 0.f;

    // prologue: async-fill tile kt=0 into buf 0
    cp_async16(&As[0][lr     ][lc * 4], Xg);
    cp_async16(&As[0][lr + 64][lc * 4], Xg + (size_t)64 * KD);
    cp_async16(&Bs[0][lr     ][lc * 4], Wg);
    cp_async16(&Bs[0][lr + 64][lc * 4], Wg + (size_t)64 * KD);
    cp_commit();

    int buf = 0;
    #pragma unroll 1
    for (int kt = 0; kt < KD; kt += 16) {
        cp_wait0();
        __syncthreads();

        // stream next tile into the other buffer while computing this one
        if (kt + 16 < KD) {
            const int nb = buf ^ 1;
            cp_async16(&As[nb][lr     ][lc * 4], Xg + kt + 16);
            cp_async16(&As[nb][lr + 64][lc * 4], Xg + (size_t)64 * KD + kt + 16);
            cp_async16(&Bs[nb][lr     ][lc * 4], Wg + kt + 16);
            cp_async16(&Bs[nb][lr + 64][lc * 4], Wg + (size_t)64 * KD + kt + 16);
            cp_commit();
        }

        #pragma unroll
        for (int s = 0; s < 2; s++) {
            const int k0 = s * 8;
            unsigned a[4][4], b[4][2];
            #pragma unroll
            for (int mi = 0; mi < 4; mi++)
                ldsm_x4(a[mi][0], a[mi][1], a[mi][2], a[mi][3],
                        &As[buf][aRow + mi * 16][k0 + aK]);
            #pragma unroll
            for (int nj = 0; nj < 2; nj++) {
                unsigned r0, r1, r2, r3;
                ldsm_x4(r0, r1, r2, r3, &Bs[buf][bRow + nj * 16][k0 + bK]);
                b[nj * 2][0] = r0;     b[nj * 2][1] = r1;
                b[nj * 2 + 1][0] = r2; b[nj * 2 + 1][1] = r3;
            }
            #pragma unroll
            for (int mi = 0; mi < 4; mi++)
                #pragma unroll
                for (int ni = 0; ni < 4; ni++)
                    mma_tf32(acc[mi][ni], a[mi], b[ni]);
        }
        buf ^= 1;
    }
    __syncthreads();   // smem now free for colsum staging

    // epilogue: + bias, ELU, store P, fused per-CTA column partial sums.
    // C frag layout: c0=(g,2tg) c1=(g,2tg+1) c2=(g+8,2tg) c3=(g+8,2tg+1)
    float* cs = &As[0][0][0];            // staged as [16][128]
    const int colb0 = bcol * 128;
    #pragma unroll
    for (int ni = 0; ni < 4; ni++) {
        const int cloc = wn * 32 + ni * 8 + tg * 2;
        const float bl0 = bias[colb0 + cloc];
        const float bl1 = bias[colb0 + cloc + 1];
        float ca0 = 0.f, ca1 = 0.f;
        #pragma unroll
        for (int mi = 0; mi < 4; mi++) {
            const int r0 = brow * 128 + wm * 64 + mi * 16 + g;
            float x0 = acc[mi][ni][0] + bl0, x1 = acc[mi][ni][1] + bl1;
            float x2 = acc[mi][ni][2] + bl0, x3 = acc[mi][ni][3] + bl1;
            float v0 = (x0 > 0.f) ? x0 : expm1f(x0);
            float v1 = (x1 > 0.f) ? x1 : expm1f(x1);
            float v2 = (x2 > 0.f) ? x2 : expm1f(x2);
            float v3 = (x3 > 0.f) ? x3 : expm1f(x3);
            *(float2*)&P[(size_t)r0 * MDIM + colb0 + cloc]       = make_float2(v0, v1);
            *(float2*)&P[(size_t)(r0 + 8) * MDIM + colb0 + cloc] = make_float2(v2, v3);
            ca0 += v0 + v2;
            ca1 += v1 + v3;
        }
        cs[(wm * 8 + g) * 128 + cloc]     = ca0;
        cs[(wm * 8 + g) * 128 + cloc + 1] = ca1;
    }
    __syncthreads();
    if (tid < 128) {
        float ssum = 0.f;
        #pragma unroll
        for (int q = 0; q < 16; q++) ssum += cs[q * 128 + tid];
        g_cparts[z][brow][colb0 + tid] = ssum;
    }
}

// ---------------- kernel 3: finish column sums (deterministic) -------------
__global__ void k_colsumB() {
    int z = blockIdx.z;
    int col = blockIdx.x * 256 + threadIdx.x;
    float acc = 0.f;
    #pragma unroll
    for (int q = 0; q < 64; q++) acc += g_cparts[z][q][col];
    g_s[z][col] = acc;
}

// ---------------- kernel 4: logits[z] = p[z] @ s[z^1] ----------------------
__global__ void k_logits() {
    int z = blockIdx.z, row = blockIdx.x, tx = threadIdx.x;
    const float* p = g_p[z] + (size_t)row * MDIM;
    const float* s = g_s[z ^ 1];
    float acc = 0.f;
    for (int k = tx; k < MDIM; k += 128) acc += p[k] * s[k];
    __shared__ float sm[128];
    sm[tx] = acc; __syncthreads();
    for (int st = 64; st > 0; st >>= 1) { if (tx < st) sm[tx] += sm[tx + st]; __syncthreads(); }
    if (tx == 0) g_logits[z][row] = sm[0];
}

// ---------------- kernel 5: softmax stats (max, sumexp) --------------------
__global__ void k_stats() {
    int z = blockIdx.x, tx = threadIdx.x;
    __shared__ float sm[1024];
    float mx = -INFINITY;
    for (int i = tx; i < NROWS; i += 1024) mx = fmaxf(mx, g_logits[z][i]);
    sm[tx] = mx; __syncthreads();
    for (int s = 512; s > 0; s >>= 1) { if (tx < s) sm[tx] = fmaxf(sm[tx], sm[tx + s]); __syncthreads(); }
    float M = sm[0]; __syncthreads();
    float se = 0.f;
    for (int i = tx; i < NROWS; i += 1024) se += expf(g_logits[z][i] - M);
    sm[tx] = se; __syncthreads();
    for (int s = 512; s > 0; s >>= 1) { if (tx < s) sm[tx] += sm[tx + s]; __syncthreads(); }
    if (tx == 0) { g_stats[z][0] = M; g_stats[z][1] = sm[0]; }
}

// ---------------- kernel 6: att = softmax(logits) @ seq (2-stage) ----------
__global__ void k_attA(const float* __restrict__ seq1, const float* __restrict__ seq2) {
    int z = blockIdx.z;
    int col = blockIdx.x * 256 + threadIdx.x;
    const float* S = z ? seq2 : seq1;
    const int r0 = blockIdx.y * 128;
    __shared__ float sw[128];
    if (threadIdx.x < 128) {
        float M = g_stats[z][0];
        float invZ = 1.f / g_stats[z][1];
        sw[threadIdx.x] = expf(g_logits[z][r0 + threadIdx.x] - M) * invZ;
    }
    __syncthreads();
    float acc = 0.f;
    #pragma unroll 4
    for (int q = 0; q < 128; q++)
        acc += sw[q] * S[(size_t)(r0 + q) * KD + col];
    g_patt[z][blockIdx.y][col] = acc;
}
__global__ void k_attB(float* __restrict__ out) {
    int z = blockIdx.z;
    int col = blockIdx.x * 256 + threadIdx.x;
    float acc = 0.f;
    #pragma unroll
    for (int q = 0; q < 64; q++) acc += g_patt[z][q][col];
    out[z * MDIM + col] = acc;
}

// ---------------- launch ---------------------------------------------------
extern "C" void kernel_launch(void* const* d_in, const int* in_sizes, int n_in,
                              void* d_out, int out_size) {
    const float* seq1 = (const float*)d_in[0];
    const float* seq2 = (const float*)d_in[1];
    const float* ctx  = (const float*)d_in[2];
    const float* Wc1  = (const float*)d_in[3];
    const float* W1   = (const float*)d_in[4];
    const float* b1   = (const float*)d_in[5];
    const float* Wc2  = (const float*)d_in[6];
    const float* W2   = (const float*)d_in[7];
    const float* b2   = (const float*)d_in[8];
    float* out = (float*)d_out;

    k_bias    <<<dim3(MDIM, 1, 2), 128>>>(b1, b2, Wc1, Wc2, ctx);
    k_gemm_elu<<<dim3(MDIM / 128, NROWS / 128, 2), 256>>>(seq1, seq2, W1, W2);
    k_colsumB <<<dim3(4, 1, 2), 256>>>();
    k_logits  <<<dim3(NROWS, 1, 2), 128>>>();
    k_stats   <<<2, 1024>>>();
    k_attA    <<<dim3(4, 64, 2), 256>>>(seq1, seq2);
    k_attB    <<<dim3(4, 1, 2), 256>>>(out);
}

// round 10
// speedup vs baseline: 1.3992x; 1.3992x over previous
#include <cuda_runtime.h>
#include <cuda_bf16.h>
#include <math.h>

// Problem constants (fixed by the dataset: a=b=8192, e1=e2=c=m=1024)
#define NROWS 8192
#define MDIM  1024
#define KD    1024

// ---------------- scratch (device globals; no allocation allowed) ----------
__device__ __nv_bfloat16 g_xb[2][NROWS * KD];   // bf16 copies of seq1/seq2 (32 MB)
__device__ __nv_bfloat16 g_wb[2][MDIM * KD];    // bf16 copies of W1/W2 (4 MB)
__device__ __nv_bfloat16 g_p[2][NROWS * MDIM];  // p1/p2 in bf16 (32 MB)
__device__ float g_bias[2][MDIM];               // b + Wc @ ctx
__device__ float g_cparts[2][64][MDIM];         // colsum partials (per 128-row chunk)
__device__ float g_s[2][MDIM];                  // s1 / s2
__device__ float g_logits[2][NROWS];            // attn logits
__device__ float g_stats[2][2];                 // {max, sumexp} per side
__device__ float g_patt[2][64][MDIM];           // weighted-colsum partials

// ---------------- cp.async helpers -----------------------------------------
__device__ __forceinline__ void cp_async16(void* smem_dst, const void* gsrc) {
    unsigned saddr = (unsigned)__cvta_generic_to_shared(smem_dst);
    asm volatile("cp.async.cg.shared.global [%0], [%1], 16;\n" :: "r"(saddr), "l"(gsrc));
}
__device__ __forceinline__ void cp_commit()  { asm volatile("cp.async.commit_group;\n"); }
__device__ __forceinline__ void cp_wait0()   { asm volatile("cp.async.wait_group 0;\n"); }

// ---------------- ldmatrix wrapper (b16 x4) ---------------------------------
__device__ __forceinline__ void ldsm_x4(unsigned& r0, unsigned& r1,
                                        unsigned& r2, unsigned& r3, const void* p) {
    unsigned addr = (unsigned)__cvta_generic_to_shared(p);
    asm volatile("ldmatrix.sync.aligned.m8n8.x4.shared.b16 {%0,%1,%2,%3}, [%4];\n"
                 : "=r"(r0), "=r"(r1), "=r"(r2), "=r"(r3) : "r"(addr));
}

// ---------------- bf16 mma.sync m16n8k16 ------------------------------------
__device__ __forceinline__ void mma_bf16(float c[4], const unsigned a[4], const unsigned b[2]) {
    asm volatile(
        "mma.sync.aligned.m16n8k16.row.col.f32.bf16.bf16.f32 "
        "{%0,%1,%2,%3}, {%4,%5,%6,%7}, {%8,%9}, {%0,%1,%2,%3};\n"
        : "+f"(c[0]), "+f"(c[1]), "+f"(c[2]), "+f"(c[3])
        : "r"(a[0]), "r"(a[1]), "r"(a[2]), "r"(a[3]), "r"(b[0]), "r"(b[1]));
}

// ---------------- kernel 0: fp32 -> bf16 conversion ------------------------
// which: 0 -> g_xb[z] (NROWS*KD elems), 1 -> g_wb[z] (MDIM*KD elems).
__global__ void k_cvt(const float4* __restrict__ src, int z, int which, int n4) {
    __nv_bfloat162* dst = (which == 0) ? (__nv_bfloat162*)g_xb[z]
                                       : (__nv_bfloat162*)g_wb[z];
    int idx = blockIdx.x * blockDim.x * 4 + threadIdx.x;
    #pragma unroll
    for (int j = 0; j < 4; j++, idx += blockDim.x) {
        if (idx < n4) {
            float4 v = src[idx];
            dst[idx * 2]     = __floats2bfloat162_rn(v.x, v.y);
            dst[idx * 2 + 1] = __floats2bfloat162_rn(v.z, v.w);
        }
    }
}

// ---------------- kernel 1: bias[j] = b[j] + sum_c Wc[j,c]*ctx[c] ----------
__global__ void k_bias(const float* __restrict__ b1, const float* __restrict__ b2,
                       const float* __restrict__ Wc1, const float* __restrict__ Wc2,
                       const float* __restrict__ ctx) {
    int z = blockIdx.z, j = blockIdx.x, tx = threadIdx.x;
    const float* W = z ? Wc2 : Wc1;
    const float* b = z ? b2 : b1;
    float acc = 0.f;
    for (int c = tx; c < KD; c += 128) acc += W[j * KD + c] * ctx[c];
    __shared__ float sm[128];
    sm[tx] = acc; __syncthreads();
    for (int s = 64; s > 0; s >>= 1) { if (tx < s) sm[tx] += sm[tx + s]; __syncthreads(); }
    if (tx == 0) g_bias[z][j] = b[j] + sm[0];
}

// ---------------- kernel 2: P = elu(X @ W^T + bias), fused colsum ----------
// bf16 inputs, fp32 accumulate. CTA tile 128x128, KTILE=32, 256 threads =
// 8 warps; warp tile 64x32. ldmatrix fragments (PTX-ISA-verified mapping),
// cp.async double-buffered. Smem rows stride 40 halves = 80 B
// (16B-aligned rows; ldmatrix phases conflict-free).
__global__ void __launch_bounds__(256, 2)
k_gemm_elu() {
    const int z = blockIdx.z;
    const __nv_bfloat16* X = g_xb[z];
    const __nv_bfloat16* W = g_wb[z];
    __nv_bfloat16* P = g_p[z];
    const float* bias = g_bias[z];

    __shared__ __align__(16) __nv_bfloat16 As[2][128][40];  // X tile, k 32->40
    __shared__ __align__(16) __nv_bfloat16 Bs[2][128][40];  // W tile, n-major

    const int tid  = threadIdx.x;
    const int brow = blockIdx.y, bcol = blockIdx.x;
    const int lr = tid >> 2, lc = tid & 3;         // cp.async fill mapping
    const int warp = tid >> 5, lane = tid & 31;
    const int g = lane >> 2, tg = lane & 3;        // mma lane decomposition
    const int wm = warp & 1, wn = warp >> 1;

    // ldmatrix lane->tile decomposition: t = lane>>3 (tile), r = lane&7 (row)
    const int t = lane >> 3, r = lane & 7;
    const int ldRow = (t & 1) * 8 + r;             // row within 16-row group
    const int ldK   = (t >> 1) * 8;                // k offset (halves) within k16

    const __nv_bfloat16* Xg = X + (size_t)(brow * 128 + lr) * KD + lc * 8;
    const __nv_bfloat16* Wg = W + (size_t)(bcol * 128 + lr) * KD + lc * 8;

    float acc[4][4][4];
    #pragma unroll
    for (int mi = 0; mi < 4; mi++)
        #pragma unroll
        for (int ni = 0; ni < 4; ni++)
            #pragma unroll
            for (int q = 0; q < 4; q++) acc[mi][ni][q] = 0.f;

    // prologue: async-fill tile kt=0 into buf 0
    cp_async16(&As[0][lr     ][lc * 8], Xg);
    cp_async16(&As[0][lr + 64][lc * 8], Xg + (size_t)64 * KD);
    cp_async16(&Bs[0][lr     ][lc * 8], Wg);
    cp_async16(&Bs[0][lr + 64][lc * 8], Wg + (size_t)64 * KD);
    cp_commit();

    int buf = 0;
    #pragma unroll 1
    for (int kt = 0; kt < KD; kt += 32) {
        cp_wait0();
        __syncthreads();

        // stream next tile into the other buffer while computing this one
        if (kt + 32 < KD) {
            const int nb = buf ^ 1;
            cp_async16(&As[nb][lr     ][lc * 8], Xg + kt + 32);
            cp_async16(&As[nb][lr + 64][lc * 8], Xg + (size_t)64 * KD + kt + 32);
            cp_async16(&Bs[nb][lr     ][lc * 8], Wg + kt + 32);
            cp_async16(&Bs[nb][lr + 64][lc * 8], Wg + (size_t)64 * KD + kt + 32);
            cp_commit();
        }

        #pragma unroll
        for (int s = 0; s < 2; s++) {
            const int k0 = s * 16;
            unsigned a[4][4], b[4][2];
            // A: per 16x16 tile, one ldsm.x4 (regs r0..r3 = a0..a3 exactly)
            #pragma unroll
            for (int mi = 0; mi < 4; mi++)
                ldsm_x4(a[mi][0], a[mi][1], a[mi][2], a[mi][3],
                        &As[buf][wm * 64 + mi * 16 + ldRow][k0 + ldK]);
            // B: one ldsm.x4 covers two n8 tiles (16 n-rows x k16);
            // n8 tile 0 = {r0, r2}, n8 tile 1 = {r1, r3} (PTX-ISA verified)
            #pragma unroll
            for (int nj = 0; nj < 2; nj++) {
                unsigned r0, r1, r2, r3;
                ldsm_x4(r0, r1, r2, r3,
                        &Bs[buf][wn * 32 + nj * 16 + ldRow][k0 + ldK]);
                b[nj * 2][0] = r0;     b[nj * 2][1] = r2;
                b[nj * 2 + 1][0] = r1; b[nj * 2 + 1][1] = r3;
            }
            #pragma unroll
            for (int mi = 0; mi < 4; mi++)
                #pragma unroll
                for (int ni = 0; ni < 4; ni++)
                    mma_bf16(acc[mi][ni], a[mi], b[ni]);
        }
        buf ^= 1;
    }
    __syncthreads();   // smem now free for colsum staging

    // epilogue: + bias, ELU, store P (bf16), fused column partial sums.
    // C frag layout: c0=(g,2tg) c1=(g,2tg+1) c2=(g+8,2tg) c3=(g+8,2tg+1)
    float* cs = (float*)&As[0][0][0];    // staged as [16][128] floats (8 KB)
    const int colb0 = bcol * 128;
    #pragma unroll
    for (int ni = 0; ni < 4; ni++) {
        const int cloc = wn * 32 + ni * 8 + tg * 2;
        const float bl0 = bias[colb0 + cloc];
        const float bl1 = bias[colb0 + cloc + 1];
        float ca0 = 0.f, ca1 = 0.f;
        #pragma unroll
        for (int mi = 0; mi < 4; mi++) {
            const int r0 = brow * 128 + wm * 64 + mi * 16 + g;
            float x0 = acc[mi][ni][0] + bl0, x1 = acc[mi][ni][1] + bl1;
            float x2 = acc[mi][ni][2] + bl0, x3 = acc[mi][ni][3] + bl1;
            float v0 = (x0 > 0.f) ? x0 : expm1f(x0);
            float v1 = (x1 > 0.f) ? x1 : expm1f(x1);
            float v2 = (x2 > 0.f) ? x2 : expm1f(x2);
            float v3 = (x3 > 0.f) ? x3 : expm1f(x3);
            *(__nv_bfloat162*)&P[(size_t)r0 * MDIM + colb0 + cloc] =
                __floats2bfloat162_rn(v0, v1);
            *(__nv_bfloat162*)&P[(size_t)(r0 + 8) * MDIM + colb0 + cloc] =
                __floats2bfloat162_rn(v2, v3);
            ca0 += v0 + v2;
            ca1 += v1 + v3;
        }
        cs[(wm * 8 + g) * 128 + cloc]     = ca0;
        cs[(wm * 8 + g) * 128 + cloc + 1] = ca1;
    }
    __syncthreads();
    if (tid < 128) {
        float ssum = 0.f;
        #pragma unroll
        for (int q = 0; q < 16; q++) ssum += cs[q * 128 + tid];
        g_cparts[z][brow][colb0 + tid] = ssum;
    }
}

// ---------------- kernel 3: finish column sums (deterministic) -------------
__global__ void k_colsumB() {
    int z = blockIdx.z;
    int col = blockIdx.x * 256 + threadIdx.x;
    float acc = 0.f;
    #pragma unroll
    for (int q = 0; q < 64; q++) acc += g_cparts[z][q][col];
    g_s[z][col] = acc;
}

// ---------------- kernel 4: logits[z] = p[z] @ s[z^1] ----------------------
// Warp per row; 4 independent uint4 (8-half) loads per lane (MLP=4);
// shuffle reduction; s cached in smem.
__global__ void k_logits() {
    const int z = blockIdx.z, tx = threadIdx.x;
    const int warp = tx >> 5, lane = tx & 31;
    __shared__ float ss[MDIM];
    const float* s = g_s[z ^ 1];
    #pragma unroll
    for (int j = 0; j < 4; j++) ss[j * 256 + tx] = s[j * 256 + tx];
    __syncthreads();

    const int row = blockIdx.x * 8 + warp;
    const uint4* p = (const uint4*)(g_p[z] + (size_t)row * MDIM);
    uint4 v[4];
    #pragma unroll
    for (int it = 0; it < 4; it++) v[it] = p[it * 32 + lane];   // MLP=4

    float acc = 0.f;
    #pragma unroll
    for (int it = 0; it < 4; it++) {
        const int k0 = (it * 32 + lane) * 8;
        const __nv_bfloat162* h = (const __nv_bfloat162*)&v[it];
        #pragma unroll
        for (int j = 0; j < 4; j++) {
            float2 f = __bfloat1622float2(h[j]);
            acc += f.x * ss[k0 + j * 2] + f.y * ss[k0 + j * 2 + 1];
        }
    }
    #pragma unroll
    for (int o = 16; o > 0; o >>= 1) acc += __shfl_xor_sync(0xffffffffu, acc, o);
    if (lane == 0) g_logits[z][row] = acc;
}

// ---------------- kernel 5: softmax stats (max, sumexp) --------------------
__global__ void k_stats() {
    int z = blockIdx.x, tx = threadIdx.x;
    __shared__ float sm[1024];
    float mx = -INFINITY;
    for (int i = tx; i < NROWS; i += 1024) mx = fmaxf(mx, g_logits[z][i]);
    sm[tx] = mx; __syncthreads();
    for (int s = 512; s > 0; s >>= 1) { if (tx < s) sm[tx] = fmaxf(sm[tx], sm[tx + s]); __syncthreads(); }
    float M = sm[0]; __syncthreads();
    float se = 0.f;
    for (int i = tx; i < NROWS; i += 1024) se += expf(g_logits[z][i] - M);
    sm[tx] = se; __syncthreads();
    for (int s = 512; s > 0; s >>= 1) { if (tx < s) sm[tx] += sm[tx + s]; __syncthreads(); }
    if (tx == 0) { g_stats[z][0] = M; g_stats[z][1] = sm[0]; }
}

// ---------------- kernel 6: att = softmax(logits) @ seq (2-stage, fp32) ----
__global__ void k_attA(const float* __restrict__ seq1, const float* __restrict__ seq2) {
    int z = blockIdx.z;
    int col = blockIdx.x * 256 + threadIdx.x;
    const float* S = z ? seq2 : seq1;
    const int r0 = blockIdx.y * 128;
    __shared__ float sw[128];
    if (threadIdx.x < 128) {
        float M = g_stats[z][0];
        float invZ = 1.f / g_stats[z][1];
        sw[threadIdx.x] = expf(g_logits[z][r0 + threadIdx.x] - M) * invZ;
    }
    __syncthreads();
    float acc = 0.f;
    #pragma unroll 4
    for (int q = 0; q < 128; q++)
        acc += sw[q] * S[(size_t)(r0 + q) * KD + col];
    g_patt[z][blockIdx.y][col] = acc;
}
__global__ void k_attB(float* __restrict__ out) {
    int z = blockIdx.z;
    int col = blockIdx.x * 256 + threadIdx.x;
    float acc = 0.f;
    #pragma unroll
    for (int q = 0; q < 64; q++) acc += g_patt[z][q][col];
    out[z * MDIM + col] = acc;
}

// ---------------- launch ---------------------------------------------------
extern "C" void kernel_launch(void* const* d_in, const int* in_sizes, int n_in,
                              void* d_out, int out_size) {
    const float* seq1 = (const float*)d_in[0];
    const float* seq2 = (const float*)d_in[1];
    const float* ctx  = (const float*)d_in[2];
    const float* Wc1  = (const float*)d_in[3];
    const float* W1   = (const float*)d_in[4];
    const float* b1   = (const float*)d_in[5];
    const float* Wc2  = (const float*)d_in[6];
    const float* W2   = (const float*)d_in[7];
    const float* b2   = (const float*)d_in[8];
    float* out = (float*)d_out;

    const int nX4 = NROWS * KD / 4, nW4 = MDIM * KD / 4;
    k_cvt<<<nX4 / 1024, 256>>>((const float4*)seq1, 0, 0, nX4);
    k_cvt<<<nX4 / 1024, 256>>>((const float4*)seq2, 1, 0, nX4);
    k_cvt<<<nW4 / 1024, 256>>>((const float4*)W1,   0, 1, nW4);
    k_cvt<<<nW4 / 1024, 256>>>((const float4*)W2,   1, 1, nW4);

    k_bias    <<<dim3(MDIM, 1, 2), 128>>>(b1, b2, Wc1, Wc2, ctx);
    k_gemm_elu<<<dim3(MDIM / 128, NROWS / 128, 2), 256>>>();
    k_colsumB <<<dim3(4, 1, 2), 256>>>();
    k_logits  <<<dim3(NROWS / 8, 1, 2), 256>>>();
    k_stats   <<<2, 1024>>>();
    k_attA    <<<dim3(4, 64, 2), 256>>>(seq1, seq2);
    k_attB    <<<dim3(4, 1, 2), 256>>>(out);
}